// round 13
// baseline (speedup 1.0000x reference)
#include <cuda_runtime.h>

#define NPTS 250000
#define BATCH 2
#define NCELL (1024 * 1024)
#define NCHUNK 2048            // fill chunks of 512 cells
#define ZMB 512                // zmean partial slots (= bin grid.x)
#define PPB 64
#define MTHREADS 128
#define NTILE ((NPTS + PPB - 1) / PPB)   // 3907
#define SMEM_BYTES 37376       // 9344 floats

typedef unsigned long long ull;

__device__ float g_part[BATCH][2][ZMB];   // zmean partials
__device__ float g_zm[BATCH];             // final z mean
__device__ float g_fold[4864];            // W1f|t1|W2f|t2
__device__ int   g_cnt[BATCH][NCELL];     // histogram (self-cleaned by pfe fill)
__device__ int   g_cursor[BATCH][NCELL];  // chunk-local prefixes -> cursors
__device__ int   g_cell[BATCH][NPTS];     // cell per point (-1 if masked out)
__device__ int   g_idx[BATCH][NPTS];      // cell-sorted point ids
__device__ int   g_bsum[BATCH][256];      // per-4096-cell-chunk sums
__device__ int   g_nvalid[BATCH];

__device__ __forceinline__ ull dup2(float a) {
    ull r; asm("mov.b64 %0, {%1, %1};" : "=l"(r) : "f"(a)); return r;
}
__device__ __forceinline__ ull fma2(ull a, ull b, ull c) {
    ull d; asm("fma.rn.f32x2 %0, %1, %2, %3;" : "=l"(d) : "l"(a), "l"(b), "l"(c)); return d;
}
__device__ __forceinline__ void unpk(ull v, float& lo, float& hi) {
    asm("mov.b64 {%0, %1}, %2;" : "=f"(lo), "=f"(hi) : "l"(v));
}

// exact replica of reference binning
__device__ __forceinline__ int cell_of(float x, float y) {
    const float fx = __fdiv_rn(x - (-51.2f), 0.1f);
    const float fy = __fdiv_rn(y - (-51.2f), 0.1f);
    int px = min(max((int)floorf(fx), 0), 1023);
    int py = min(max((int)floorf(fy), 0), 1023);
    return py * 1024 + px;
}

// ---------------------------------------------------------------------------
// bin: cell per point + histogram + zmean partials + BN fold
// ---------------------------------------------------------------------------
__global__ void bin_kernel(const float* __restrict__ points,
                           const int* __restrict__ mask,
                           const float* __restrict__ W1, const float* __restrict__ g1,
                           const float* __restrict__ b1, const float* __restrict__ m1,
                           const float* __restrict__ v1,
                           const float* __restrict__ W2, const float* __restrict__ g2,
                           const float* __restrict__ b2, const float* __restrict__ m2,
                           const float* __restrict__ v2) {
    const int b = blockIdx.y, bx = blockIdx.x, tid = threadIdx.x;
    float s = 0.f, c = 0.f;
    for (int i = bx * 256 + tid; i < NPTS; i += ZMB * 256) {
        const float* pp = points + ((size_t)b * NPTS + i) * 5;
        const int cl = cell_of(pp[0], pp[1]);
        const int mk = mask[(size_t)b * NPTS + i] != 0;
        g_cell[b][i] = mk ? cl : -1;
        if (mk) {
            atomicAdd(&g_cnt[b][cl], 1);
            s += pp[2];
            c += 1.f;
        }
    }
#pragma unroll
    for (int o = 16; o; o >>= 1) {
        s += __shfl_xor_sync(0xFFFFFFFFu, s, o);
        c += __shfl_xor_sync(0xFFFFFFFFu, c, o);
    }
    __shared__ float ss[8], sc[8];
    const int w = tid >> 5, l = tid & 31;
    if (l == 0) { ss[w] = s; sc[w] = c; }
    __syncthreads();
    if (tid == 0) {
        float S = 0.f, C = 0.f;
#pragma unroll
        for (int i = 0; i < 8; i++) { S += ss[i]; C += sc[i]; }
        g_part[b][0][bx] = S;
        g_part[b][1][bx] = C;
    }

    // BN fold (one block)
    if (bx == 0 && b == 0 && tid < 64) {
        const int ch = tid;
        const float s1 = g1[ch] * rsqrtf(v1[ch] + 1e-5f);
        const float s2 = g2[ch] * rsqrtf(v2[ch] + 1e-5f);
        g_fold[640 + ch]  = b1[ch] - m1[ch] * s1;
        g_fold[4800 + ch] = b2[ch] - m2[ch] * s2;
#pragma unroll
        for (int f = 0; f < 10; f++) g_fold[f * 64 + ch] = W1[f * 64 + ch] * s1;
        for (int k = 0; k < 64; k++) g_fold[704 + k * 64 + ch] = W2[k * 64 + ch] * s2;
    }
}

// ---------------------------------------------------------------------------
// scan1: per-4096-cell-chunk exclusive scan (warp shuffle, 4 cells/thread)
// ---------------------------------------------------------------------------
__global__ void scan1_kernel() {
    const int b = blockIdx.y, bx = blockIdx.x, tid = threadIdx.x;
    const int base = bx * 4096 + tid * 4;
    const int4 v = *(const int4*)&g_cnt[b][base];
    const int tsum = v.x + v.y + v.z + v.w;
    int s = tsum;
    const int lane = tid & 31, wid = tid >> 5;
#pragma unroll
    for (int o = 1; o < 32; o <<= 1) {
        int t = __shfl_up_sync(0xFFFFFFFFu, s, o);
        if (lane >= o) s += t;
    }
    __shared__ int wsum[32];
    if (lane == 31) wsum[wid] = s;
    __syncthreads();
    if (wid == 0) {
        int w = wsum[lane];
#pragma unroll
        for (int o = 1; o < 32; o <<= 1) {
            int t = __shfl_up_sync(0xFFFFFFFFu, w, o);
            if (lane >= o) w += t;
        }
        wsum[lane] = w;
    }
    __syncthreads();
    const int wbase = wid ? wsum[wid - 1] : 0;
    const int excl = wbase + s - tsum;
    int4 e;
    e.x = excl; e.y = e.x + v.x; e.z = e.y + v.y; e.w = e.z + v.z;
    *(int4*)&g_cursor[b][base] = e;
    if (tid == 1023) g_bsum[b][bx] = e.w + v.w;
}

// ---------------------------------------------------------------------------
// scatter: inline scan of chunk sums + zmean finalize + sorted-list build
// ---------------------------------------------------------------------------
__global__ void scatter_kernel() {
    const int b = blockIdx.y, bx = blockIdx.x, tid = threadIdx.x;
    __shared__ int s_boff[256];
    __shared__ int wsum[8];

    // inline exclusive scan of g_bsum[b][0..255]
    {
        const int v = g_bsum[b][tid];
        int s = v;
        const int lane = tid & 31, wid = tid >> 5;
#pragma unroll
        for (int o = 1; o < 32; o <<= 1) {
            int t = __shfl_up_sync(0xFFFFFFFFu, s, o);
            if (lane >= o) s += t;
        }
        if (lane == 31) wsum[wid] = s;
        __syncthreads();
        if (tid < 8) {
            int w = wsum[tid];
#pragma unroll
            for (int o = 1; o < 8; o <<= 1) {
                int t = __shfl_up_sync(0xFFu, w, o);
                if (tid >= o) w += t;
            }
            wsum[tid] = w;
        }
        __syncthreads();
        const int excl = ((tid >> 5) ? wsum[(tid >> 5) - 1] : 0) + s - v;
        s_boff[tid] = excl;
        if (bx == 0 && tid == 255) g_nvalid[b] = excl + v;
        __syncthreads();
    }

    // zmean finalize (one block per batch)
    if (bx == 0) {
        float s = g_part[b][0][tid] + g_part[b][0][tid + 256];
        float c = g_part[b][1][tid] + g_part[b][1][tid + 256];
#pragma unroll
        for (int o = 16; o; o >>= 1) {
            s += __shfl_xor_sync(0xFFFFFFFFu, s, o);
            c += __shfl_xor_sync(0xFFFFFFFFu, c, o);
        }
        __shared__ float fs[8], fc[8];
        const int w = tid >> 5, l = tid & 31;
        if (l == 0) { fs[w] = s; fc[w] = c; }
        __syncthreads();
        if (tid == 0) {
            float S = 0.f, C = 0.f;
#pragma unroll
            for (int i = 0; i < 8; i++) { S += fs[i]; C += fc[i]; }
            g_zm[b] = S / fmaxf(C, 1.0f);
        }
    }

    for (int i = bx * 256 + tid; i < NPTS; i += 256 * 256) {
        const int cl = g_cell[b][i];
        if (cl >= 0) {
            const int pos = atomicAdd(&g_cursor[b][cl], 1) + s_boff[cl >> 12];
            g_idx[b][pos] = i;
        }
    }
}

// ---------------------------------------------------------------------------
// fill one 512-cell chunk: plain zero stores on inactive quads,
// atomicMax(d,0) on active lanes (commutes with scatter-max).
// Self-cleans g_cnt so the next graph replay sees zeros.
// ---------------------------------------------------------------------------
__device__ __forceinline__ void fill_chunk(float* __restrict__ out, int b, int chunk, int tid) {
    const int cbase = chunk * 512 + tid * 4;
    const int4 cnt = *(const int4*)&g_cnt[b][cbase];
    *(int4*)&g_cnt[b][cbase] = make_int4(0, 0, 0, 0);   // self-clean
    int* dst0 = (int*)out + (((size_t)(b * 64)) << 20) + cbase;
    if ((cnt.x | cnt.y | cnt.z | cnt.w) == 0) {
        const int4 z = make_int4(0, 0, 0, 0);
#pragma unroll 8
        for (int c = 0; c < 64; c++)
            *(int4*)(dst0 + ((size_t)c << 20)) = z;
    } else {
#pragma unroll 4
        for (int c = 0; c < 64; c++) {
            int* d = dst0 + ((size_t)c << 20);
            if (cnt.x) atomicMax(d + 0, 0); else d[0] = 0;
            if (cnt.y) atomicMax(d + 1, 0); else d[1] = 0;
            if (cnt.z) atomicMax(d + 2, 0); else d[2] = 0;
            if (cnt.w) atomicMax(d + 3, 0); else d[3] = 0;
        }
    }
}

// ---------------------------------------------------------------------------
// pfe: fill-first (R6's proven structure) + small-tile compute for 6 blocks/SM.
// Phase A: 2 threads per point, 32 channels each (h2[16] = 32 regs).
// Phase B: 4 pts x 8 ch register tile (acc = 32 regs).
// ---------------------------------------------------------------------------
__global__ __launch_bounds__(MTHREADS, 6)
void pfe_kernel(const float* __restrict__ points,
                float* __restrict__ out) {
    extern __shared__ __align__(16) float smem[];
    float* W1s = smem;                  // 640
    float* t1s = smem + 640;            // 64
    float* W2s = smem + 704;            // 4096
    float* t2s = smem + 4800;           // 64
    float* h1s = smem + 4864;           // 64 rows x stride 68 (4352)
    int* sidx  = (int*)(smem + 9216);   // 64
    int* smk   = sidx + 64;             // 64

    const int tid = threadIdx.x;
    const int b = blockIdx.y;
    const int bid = blockIdx.x;

    // ---------------- fill: one chunk per block (bid < NCHUNK) --------------
    if (bid < NCHUNK) fill_chunk(out, b, bid, tid);

    const int p0 = bid * PPB;
    const int nvalid = g_nvalid[b];
    if (p0 >= nvalid) return;

    for (int i = tid; i < 4864; i += MTHREADS) smem[i] = g_fold[i];
    const float zm = g_zm[b];
    __syncthreads();

    // ---------------- Phase A: layer 1, 2 threads/point ----------------
    {
        const int p = tid & 63;          // point in block
        const int half = tid >> 6;       // channel half: 0 or 1
        const int sIdx = p0 + p;
        float aug[10];
        int cell = 0, valid = 0;
        if (sIdx < nvalid) {
            const int gi = g_idx[b][sIdx];
            const float* pp = points + ((size_t)b * NPTS + gi) * 5;
            const float x = pp[0], y = pp[1], z = pp[2];
            aug[3] = pp[3]; aug[4] = pp[4];
            const float fx = __fdiv_rn(x - (-51.2f), 0.1f);
            const float fy = __fdiv_rn(y - (-51.2f), 0.1f);
            int px = min(max((int)floorf(fx), 0), 1023);
            int py = min(max((int)floorf(fy), 0), 1023);
            const float pxf = (float)px, pyf = (float)py;
            aug[0] = x; aug[1] = y; aug[2] = z;
            aug[5] = x - (pxf * 0.1f + (-51.2f) + 0.05f);
            aug[6] = y - (pyf * 0.1f + (-51.2f) + 0.05f);
            aug[7] = z - zm;
            aug[8] = x - (pxf * 0.1f + (-51.2f));
            aug[9] = y - (pyf * 0.1f + (-51.2f));
            cell = py * 1024 + px;
            valid = 1;
        } else {
#pragma unroll
            for (int f = 0; f < 10; f++) aug[f] = 0.f;
        }
        if (half == 0) { sidx[p] = cell; smk[p] = valid; }

        ull h2[16];                      // 16 channel-pairs = 32 channels
        {
            const ulonglong2* t1q = (const ulonglong2*)(t1s + half * 32);
#pragma unroll
            for (int q = 0; q < 8; q++) {
                const ulonglong2 t = t1q[q];
                h2[2 * q] = t.x; h2[2 * q + 1] = t.y;
            }
        }
#pragma unroll
        for (int f = 0; f < 10; f++) {
            const ull a = dup2(aug[f]);
#pragma unroll
            for (int q = 0; q < 8; q++) {
                const ulonglong2 w = *(const ulonglong2*)(W1s + f * 64 + half * 32 + q * 4);
                h2[2 * q]     = fma2(a, w.x, h2[2 * q]);
                h2[2 * q + 1] = fma2(a, w.y, h2[2 * q + 1]);
            }
        }
#pragma unroll
        for (int c2 = 0; c2 < 16; c2++) {
            float lo, hi; unpk(h2[c2], lo, hi);
            const int row = half * 32 + 2 * c2;
            h1s[row * 68 + p]       = fmaxf(lo, 0.f);
            h1s[(row + 1) * 68 + p] = fmaxf(hi, 0.f);
        }
    }
    __syncthreads();

    // ---------------- Phase B: layer 2, 4 pts x 8 ch register tile ----------
    const int chg = tid & 7;             // channels chg*8 .. +7
    const int ptg = tid >> 3;            // points  ptg*4 .. +3 (0..15)
    const float* hbase = h1s + ptg * 4;
    const ull* W2u = (const ull*)W2s;
    const ulonglong2* t2q = (const ulonglong2*)t2s;

    ull acc[4][4];
    {
        const ulonglong2 tA = t2q[chg * 2 + 0];
        const ulonglong2 tB = t2q[chg * 2 + 1];
#pragma unroll
        for (int i = 0; i < 4; i++) {
            acc[i][0] = tA.x; acc[i][1] = tA.y; acc[i][2] = tB.x; acc[i][3] = tB.y;
        }
    }

#pragma unroll 4
    for (int k = 0; k < 64; k++) {
        const float4 hv = *(const float4*)(hbase + k * 68);
        const ulonglong2 wA = *(const ulonglong2*)(W2u + k * 32 + chg * 4);
        const ulonglong2 wB = *(const ulonglong2*)(W2u + k * 32 + chg * 4 + 2);
        const ull hd[4] = {dup2(hv.x), dup2(hv.y), dup2(hv.z), dup2(hv.w)};
#pragma unroll
        for (int i = 0; i < 4; i++) {
            acc[i][0] = fma2(hd[i], wA.x, acc[i][0]);
            acc[i][1] = fma2(hd[i], wA.y, acc[i][1]);
            acc[i][2] = fma2(hd[i], wB.x, acc[i][2]);
            acc[i][3] = fma2(hd[i], wB.y, acc[i][3]);
        }
    }

    // ---------------- epilogue: run-length dedup + guarded scatter-max ------
    int* obase = (int*)out + (((size_t)(b * 64 + chg * 8)) << 20);
    const int base = ptg * 4;

    float rm[8];
#pragma unroll
    for (int j = 0; j < 4; j++) unpk(acc[0][j], rm[2 * j], rm[2 * j + 1]);
    int cur = sidx[base];
    int curv = smk[base];

#pragma unroll
    for (int i = 1; i < 4; i++) {
        const int v = smk[base + i];
        const int cl = sidx[base + i];
        float f[8];
#pragma unroll
        for (int j = 0; j < 4; j++) unpk(acc[i][j], f[2 * j], f[2 * j + 1]);
        if (v && cl == cur) {
#pragma unroll
            for (int t = 0; t < 8; t++) rm[t] = fmaxf(rm[t], f[t]);
        } else {
            if (curv) {
                int* ob = obase + cur;
#pragma unroll
                for (int t = 0; t < 8; t++)
                    if (rm[t] > 0.f) atomicMax(ob + ((size_t)t << 20), __float_as_int(rm[t]));
            }
#pragma unroll
            for (int t = 0; t < 8; t++) rm[t] = f[t];
            cur = cl;
            curv = v;
        }
    }
    if (curv) {
        int* ob = obase + cur;
#pragma unroll
        for (int t = 0; t < 8; t++)
            if (rm[t] > 0.f) atomicMax(ob + ((size_t)t << 20), __float_as_int(rm[t]));
    }
}

// ---------------------------------------------------------------------------
extern "C" void kernel_launch(void* const* d_in, const int* in_sizes, int n_in,
                              void* d_out, int out_size) {
    const float* points = (const float*)d_in[0];
    const int* pmask    = (const int*)d_in[1];
    const float* W1 = (const float*)d_in[2];
    const float* g1 = (const float*)d_in[3];
    const float* b1 = (const float*)d_in[4];
    const float* m1 = (const float*)d_in[5];
    const float* v1 = (const float*)d_in[6];
    const float* W2 = (const float*)d_in[7];
    const float* g2 = (const float*)d_in[8];
    const float* b2 = (const float*)d_in[9];
    const float* m2 = (const float*)d_in[10];
    const float* v2 = (const float*)d_in[11];
    float* out = (float*)d_out;

    cudaFuncSetAttribute(pfe_kernel, cudaFuncAttributeMaxDynamicSharedMemorySize, SMEM_BYTES);

    dim3 bg(ZMB, BATCH);
    bin_kernel<<<bg, 256>>>(points, pmask, W1, g1, b1, m1, v1,
                            W2, g2, b2, m2, v2);

    dim3 s1g(256, BATCH);
    scan1_kernel<<<s1g, 1024>>>();

    dim3 scg(256, BATCH);
    scatter_kernel<<<scg, 256>>>();

    dim3 mg(NTILE, BATCH);
    pfe_kernel<<<mg, MTHREADS, SMEM_BYTES>>>(points, out);
}

// round 14
// speedup vs baseline: 1.4546x; 1.4546x over previous
#include <cuda_runtime.h>

#define NPTS 250000
#define BATCH 2
#define NCELL (1024 * 1024)
#define NCHUNK 2048            // fill chunks of 512 cells
#define ZMB 64                 // zmean blocks per batch
#define PPB 128
#define MTHREADS 128
#define NTILE ((NPTS + PPB - 1) / PPB)   // 1954
#define SMEM_BYTES 54272       // 13568 floats

typedef unsigned long long ull;

__device__ float g_part[BATCH][2][ZMB];   // zmean partials
__device__ float g_fold[4864];            // W1f|t1|W2f|t2
__device__ int   g_cnt[BATCH][NCELL];     // per-cell histogram
__device__ int   g_cursor[BATCH][NCELL];  // chunk-local exclusive prefixes -> cursors
__device__ int   g_cell[BATCH][NPTS];     // cell per point (-1 if masked out)
__device__ int   g_idx[BATCH][NPTS];      // cell-sorted point ids
__device__ int   g_bsum[BATCH][256];
__device__ int   g_boff[BATCH][256];
__device__ int   g_nvalid[BATCH];

__device__ __forceinline__ ull dup2(float a) {
    ull r; asm("mov.b64 %0, {%1, %1};" : "=l"(r) : "f"(a)); return r;
}
__device__ __forceinline__ ull fma2(ull a, ull b, ull c) {
    ull d; asm("fma.rn.f32x2 %0, %1, %2, %3;" : "=l"(d) : "l"(a), "l"(b), "l"(c)); return d;
}
__device__ __forceinline__ void unpk(ull v, float& lo, float& hi) {
    asm("mov.b64 {%0, %1}, %2;" : "=f"(lo), "=f"(hi) : "l"(v));
}

// exact replica of reference binning
__device__ __forceinline__ int cell_of(float x, float y) {
    const float fx = __fdiv_rn(x - (-51.2f), 0.1f);
    const float fy = __fdiv_rn(y - (-51.2f), 0.1f);
    int px = min(max((int)floorf(fx), 0), 1023);
    int py = min(max((int)floorf(fy), 0), 1023);
    return py * 1024 + px;
}

// ---------------------------------------------------------------------------
// zero g_cnt (8MB) + BN fold
// ---------------------------------------------------------------------------
__global__ void zcnt_kernel(const float* __restrict__ W1, const float* __restrict__ g1,
                            const float* __restrict__ b1, const float* __restrict__ m1,
                            const float* __restrict__ v1,
                            const float* __restrict__ W2, const float* __restrict__ g2,
                            const float* __restrict__ b2, const float* __restrict__ m2,
                            const float* __restrict__ v2) {
    const int bid = blockIdx.x, tid = threadIdx.x;
    int4* cnt4 = (int4*)g_cnt;
    const int4 zi4 = make_int4(0, 0, 0, 0);
    const int ctot4 = BATCH * NCELL / 4;
    for (int i = bid * 256 + tid; i < ctot4; i += 512 * 256) cnt4[i] = zi4;

    if (bid == 0 && tid < 64) {
        const int c = tid;
        const float s1 = g1[c] * rsqrtf(v1[c] + 1e-5f);
        const float s2 = g2[c] * rsqrtf(v2[c] + 1e-5f);
        g_fold[640 + c]  = b1[c] - m1[c] * s1;
        g_fold[4800 + c] = b2[c] - m2[c] * s2;
#pragma unroll
        for (int f = 0; f < 10; f++) g_fold[f * 64 + c] = W1[f * 64 + c] * s1;
        for (int k = 0; k < 64; k++) g_fold[704 + k * 64 + c] = W2[k * 64 + c] * s2;
    }
}

// ---------------------------------------------------------------------------
// bin: cell per point + histogram + zmean partials
// ---------------------------------------------------------------------------
__global__ void bin_kernel(const float* __restrict__ points,
                           const int* __restrict__ mask) {
    const int b = blockIdx.y, tid = threadIdx.x;
    float s = 0.f, c = 0.f;
    for (int i = blockIdx.x * 256 + tid; i < NPTS; i += ZMB * 256) {
        const float* pp = points + ((size_t)b * NPTS + i) * 5;
        const int cl = cell_of(pp[0], pp[1]);
        const int mk = mask[(size_t)b * NPTS + i] != 0;
        g_cell[b][i] = mk ? cl : -1;
        if (mk) {
            atomicAdd(&g_cnt[b][cl], 1);
            s += pp[2];
            c += 1.f;
        }
    }
#pragma unroll
    for (int o = 16; o; o >>= 1) {
        s += __shfl_xor_sync(0xFFFFFFFFu, s, o);
        c += __shfl_xor_sync(0xFFFFFFFFu, c, o);
    }
    __shared__ float ss[8], sc[8];
    const int w = tid >> 5, l = tid & 31;
    if (l == 0) { ss[w] = s; sc[w] = c; }
    __syncthreads();
    if (tid == 0) {
        float S = 0.f, C = 0.f;
#pragma unroll
        for (int i = 0; i < 8; i++) { S += ss[i]; C += sc[i]; }
        g_part[b][0][blockIdx.x] = S;
        g_part[b][1][blockIdx.x] = C;
    }
}

// ---------------------------------------------------------------------------
// scan1: per-4096-cell-chunk exclusive scan (warp-shuffle), 4 cells/thread
// ---------------------------------------------------------------------------
__global__ void scan1_kernel() {
    const int b = blockIdx.y, bx = blockIdx.x, tid = threadIdx.x;
    const int base = bx * 4096 + tid * 4;
    const int4 v = *(const int4*)&g_cnt[b][base];
    const int tsum = v.x + v.y + v.z + v.w;
    int s = tsum;
    const int lane = tid & 31, wid = tid >> 5;
#pragma unroll
    for (int o = 1; o < 32; o <<= 1) {
        int t = __shfl_up_sync(0xFFFFFFFFu, s, o);
        if (lane >= o) s += t;
    }
    __shared__ int wsum[32];
    if (lane == 31) wsum[wid] = s;
    __syncthreads();
    if (wid == 0) {
        int w = wsum[lane];
#pragma unroll
        for (int o = 1; o < 32; o <<= 1) {
            int t = __shfl_up_sync(0xFFFFFFFFu, w, o);
            if (lane >= o) w += t;
        }
        wsum[lane] = w;
    }
    __syncthreads();
    const int wbase = wid ? wsum[wid - 1] : 0;
    const int excl = wbase + s - tsum;
    int4 e;
    e.x = excl; e.y = e.x + v.x; e.z = e.y + v.y; e.w = e.z + v.z;
    *(int4*)&g_cursor[b][base] = e;
    if (tid == 1023) g_bsum[b][bx] = e.w + v.w;
}

// ---------------------------------------------------------------------------
// scan2: exclusive scan of 256 chunk sums per batch
// ---------------------------------------------------------------------------
__global__ void scan2_kernel() {
    const int b = blockIdx.y, tid = threadIdx.x;
    const int v = g_bsum[b][tid];
    int s = v;
    const int lane = tid & 31, wid = tid >> 5;
#pragma unroll
    for (int o = 1; o < 32; o <<= 1) {
        int t = __shfl_up_sync(0xFFFFFFFFu, s, o);
        if (lane >= o) s += t;
    }
    __shared__ int wsum[8];
    if (lane == 31) wsum[wid] = s;
    __syncthreads();
    if (wid == 0 && lane < 8) {
        int w = wsum[lane];
#pragma unroll
        for (int o = 1; o < 8; o <<= 1) {
            int t = __shfl_up_sync(0xFFu, w, o);
            if (lane >= o) w += t;
        }
        wsum[lane] = w;
    }
    __syncthreads();
    const int excl = (wid ? wsum[wid - 1] : 0) + s - v;
    g_boff[b][tid] = excl;
    if (tid == 255) g_nvalid[b] = excl + v;
}

// ---------------------------------------------------------------------------
// scatter: build cell-sorted point id list (chunk offset added on the fly)
// ---------------------------------------------------------------------------
__global__ void scatter_kernel() {
    const int b = blockIdx.y;
    for (int i = blockIdx.x * 256 + threadIdx.x; i < NPTS; i += 128 * 256) {
        const int cl = g_cell[b][i];
        if (cl >= 0) {
            const int pos = atomicAdd(&g_cursor[b][cl], 1) + g_boff[b][cl >> 12];
            g_idx[b][pos] = i;
        }
    }
}

// ---------------------------------------------------------------------------
// Fused fill + PFN + scatter-max.
// Fill: zero 512MB output. Inactive cells: plain st.128 (pfe never touches
// them). Active cells: RED.MAX(addr,0) — commutes with pfe's scatter-max,
// so NO ordering between fill and compute is needed.
// ---------------------------------------------------------------------------
__global__ __launch_bounds__(MTHREADS, 4)
void pfe_kernel(const float* __restrict__ points,
                float* __restrict__ out) {
    const int tid = threadIdx.x;
    const int b = blockIdx.y;

    // ---------------- fill phase ----------------
    for (int chunk = blockIdx.x; chunk < NCHUNK; chunk += NTILE) {
        const int cbase = chunk * 512 + tid * 4;
        const int4 cnt = *(const int4*)&g_cnt[b][cbase];
        int* dst0 = (int*)out + (((size_t)(b * 64)) << 20) + cbase;
        if ((cnt.x | cnt.y | cnt.z | cnt.w) == 0) {
            const int4 z = make_int4(0, 0, 0, 0);
#pragma unroll 8
            for (int c = 0; c < 64; c++)
                *(int4*)(dst0 + ((size_t)c << 20)) = z;
        } else {
#pragma unroll 4
            for (int c = 0; c < 64; c++) {
                int* d = dst0 + ((size_t)c << 20);
                if (cnt.x) atomicMax(d + 0, 0); else d[0] = 0;
                if (cnt.y) atomicMax(d + 1, 0); else d[1] = 0;
                if (cnt.z) atomicMax(d + 2, 0); else d[2] = 0;
                if (cnt.w) atomicMax(d + 3, 0); else d[3] = 0;
            }
        }
    }

    // ---------------- compute phase ----------------
    const int nvalid = g_nvalid[b];
    const int p0 = blockIdx.x * PPB;
    if (p0 >= nvalid) return;

    extern __shared__ __align__(16) float smem[];
    float* W1s = smem;                  // 640
    float* t1s = smem + 640;            // 64
    float* W2s = smem + 704;            // 4096
    float* t2s = smem + 4800;           // 64
    float* h1s = smem + 4864;           // 64 rows x stride 132
    int* sidx  = (int*)(smem + 13312);  // 128
    int* smk   = sidx + 128;            // 128
    __shared__ float zred;

    for (int i = tid; i < 4864; i += MTHREADS) smem[i] = g_fold[i];
    if (tid < 32) {
        float s = g_part[b][0][tid] + g_part[b][0][tid + 32];
        float c = g_part[b][1][tid] + g_part[b][1][tid + 32];
#pragma unroll
        for (int o = 16; o; o >>= 1) {
            s += __shfl_xor_sync(0xFFFFFFFFu, s, o);
            c += __shfl_xor_sync(0xFFFFFFFFu, c, o);
        }
        if (tid == 0) zred = s / fmaxf(c, 1.0f);
    }
    __syncthreads();
    const float zm = zred;

    // ---------------- Phase A (gather sorted points) ----------------
    {
        const int s = p0 + tid;
        float aug[10];
        int cell = 0, valid = 0;
        if (s < nvalid) {
            const int gi = g_idx[b][s];
            const float* pp = points + ((size_t)b * NPTS + gi) * 5;
            const float x = pp[0], y = pp[1], z = pp[2];
            aug[3] = pp[3]; aug[4] = pp[4];
            const float fx = __fdiv_rn(x - (-51.2f), 0.1f);
            const float fy = __fdiv_rn(y - (-51.2f), 0.1f);
            int px = min(max((int)floorf(fx), 0), 1023);
            int py = min(max((int)floorf(fy), 0), 1023);
            const float pxf = (float)px, pyf = (float)py;
            aug[0] = x; aug[1] = y; aug[2] = z;
            aug[5] = x - (pxf * 0.1f + (-51.2f) + 0.05f);
            aug[6] = y - (pyf * 0.1f + (-51.2f) + 0.05f);
            aug[7] = z - zm;
            aug[8] = x - (pxf * 0.1f + (-51.2f));
            aug[9] = y - (pyf * 0.1f + (-51.2f));
            cell = py * 1024 + px;
            valid = 1;
        } else {
#pragma unroll
            for (int f = 0; f < 10; f++) aug[f] = 0.f;
        }
        sidx[tid] = cell;
        smk[tid] = valid;

        ull h2[32];
        const ull* t1u = (const ull*)t1s;
#pragma unroll
        for (int c2 = 0; c2 < 32; c2++) h2[c2] = t1u[c2];
        const ull* W1u = (const ull*)W1s;
#pragma unroll
        for (int f = 0; f < 10; f++) {
            const ull a = dup2(aug[f]);
#pragma unroll
            for (int c2 = 0; c2 < 32; c2++)
                h2[c2] = fma2(a, W1u[f * 32 + c2], h2[c2]);
        }
#pragma unroll
        for (int c2 = 0; c2 < 32; c2++) {
            float lo, hi; unpk(h2[c2], lo, hi);
            h1s[(2 * c2) * 132 + tid]     = fmaxf(lo, 0.f);
            h1s[(2 * c2 + 1) * 132 + tid] = fmaxf(hi, 0.f);
        }
    }
    __syncthreads();

    // ---------------- Phase B ----------------
    const int chg = tid & 7;
    const int ptg = tid >> 3;
    const float* hbase = h1s + ptg * 8;
    const ull* W2u = (const ull*)W2s;
    const ull* t2u = (const ull*)t2s;

    ull acc[8][4];
    {
        const ull t0 = t2u[chg * 4 + 0], t1v = t2u[chg * 4 + 1];
        const ull t2v = t2u[chg * 4 + 2], t3v = t2u[chg * 4 + 3];
#pragma unroll
        for (int i = 0; i < 8; i++) {
            acc[i][0] = t0; acc[i][1] = t1v; acc[i][2] = t2v; acc[i][3] = t3v;
        }
    }

#pragma unroll 4
    for (int k = 0; k < 64; k++) {
        const float4 ha = *(const float4*)(hbase + k * 132);
        const float4 hb = *(const float4*)(hbase + k * 132 + 4);
        const ull w0 = W2u[k * 32 + chg * 4 + 0];
        const ull w1 = W2u[k * 32 + chg * 4 + 1];
        const ull w2 = W2u[k * 32 + chg * 4 + 2];
        const ull w3 = W2u[k * 32 + chg * 4 + 3];
        const ull hd[8] = {dup2(ha.x), dup2(ha.y), dup2(ha.z), dup2(ha.w),
                           dup2(hb.x), dup2(hb.y), dup2(hb.z), dup2(hb.w)};
#pragma unroll
        for (int i = 0; i < 8; i++) {
            acc[i][0] = fma2(hd[i], w0, acc[i][0]);
            acc[i][1] = fma2(hd[i], w1, acc[i][1]);
            acc[i][2] = fma2(hd[i], w2, acc[i][2]);
            acc[i][3] = fma2(hd[i], w3, acc[i][3]);
        }
    }

    // ---------------- epilogue: run-length dedup + scatter-max ----------------
    int* obase = (int*)out + (((size_t)(b * 64 + chg * 8)) << 20);
    const int base = ptg * 8;

    float rm[8];
#pragma unroll
    for (int j = 0; j < 4; j++) unpk(acc[0][j], rm[2 * j], rm[2 * j + 1]);
    int cur = sidx[base];
    int curv = smk[base];

#pragma unroll
    for (int i = 1; i < 8; i++) {
        const int v = smk[base + i];
        const int cl = sidx[base + i];
        float f[8];
#pragma unroll
        for (int j = 0; j < 4; j++) unpk(acc[i][j], f[2 * j], f[2 * j + 1]);
        if (v && cl == cur) {
#pragma unroll
            for (int t = 0; t < 8; t++) rm[t] = fmaxf(rm[t], f[t]);
        } else {
            if (curv) {
                int* ob = obase + cur;
#pragma unroll
                for (int t = 0; t < 8; t++)
                    if (rm[t] > 0.f) atomicMax(ob + ((size_t)t << 20), __float_as_int(rm[t]));
            }
#pragma unroll
            for (int t = 0; t < 8; t++) rm[t] = f[t];
            cur = cl;
            curv = v;
        }
    }
    if (curv) {
        int* ob = obase + cur;
#pragma unroll
        for (int t = 0; t < 8; t++)
            if (rm[t] > 0.f) atomicMax(ob + ((size_t)t << 20), __float_as_int(rm[t]));
    }
}

// ---------------------------------------------------------------------------
extern "C" void kernel_launch(void* const* d_in, const int* in_sizes, int n_in,
                              void* d_out, int out_size) {
    const float* points = (const float*)d_in[0];
    const int* pmask    = (const int*)d_in[1];
    const float* W1 = (const float*)d_in[2];
    const float* g1 = (const float*)d_in[3];
    const float* b1 = (const float*)d_in[4];
    const float* m1 = (const float*)d_in[5];
    const float* v1 = (const float*)d_in[6];
    const float* W2 = (const float*)d_in[7];
    const float* g2 = (const float*)d_in[8];
    const float* b2 = (const float*)d_in[9];
    const float* m2 = (const float*)d_in[10];
    const float* v2 = (const float*)d_in[11];
    float* out = (float*)d_out;

    cudaFuncSetAttribute(pfe_kernel, cudaFuncAttributeMaxDynamicSharedMemorySize, SMEM_BYTES);

    zcnt_kernel<<<512, 256>>>(W1, g1, b1, m1, v1, W2, g2, b2, m2, v2);

    dim3 bg(ZMB, BATCH);
    bin_kernel<<<bg, 256>>>(points, pmask);

    dim3 s1g(256, BATCH);
    scan1_kernel<<<s1g, 1024>>>();
    dim3 s2g(1, BATCH);
    scan2_kernel<<<s2g, 256>>>();

    dim3 scg(128, BATCH);
    scatter_kernel<<<scg, 256>>>();

    dim3 mg(NTILE, BATCH);
    pfe_kernel<<<mg, MTHREADS, SMEM_BYTES>>>(points, out);
}

// round 17
// speedup vs baseline: 1.4672x; 1.0087x over previous
#include <cuda_runtime.h>

#define NPTS 250000
#define BATCH 2
#define NCELL (1024 * 1024)
#define NCHUNK 2048            // fill chunks of 512 cells
#define ZMB 64                 // zmean blocks per batch
#define PPB 128
#define MTHREADS 128
#define NTILE ((NPTS + PPB - 1) / PPB)   // 1954
#define SMEM_BYTES 54272       // 13568 floats

typedef unsigned long long ull;

__device__ float g_part[BATCH][2][ZMB];   // zmean partials
__device__ float g_fold[4864];            // W1f|t1|W2f|t2
__device__ int   g_cnt[BATCH][NCELL];     // per-cell histogram
__device__ int   g_cursor[BATCH][NCELL];  // chunk-local exclusive prefixes -> cursors
__device__ int   g_cell[BATCH][NPTS];     // cell per point (-1 if masked out)
__device__ int   g_idx[BATCH][NPTS];      // cell-sorted point ids
__device__ int   g_bsum[BATCH][256];
__device__ int   g_nvalid[BATCH];

__device__ __forceinline__ ull dup2(float a) {
    ull r; asm("mov.b64 %0, {%1, %1};" : "=l"(r) : "f"(a)); return r;
}
__device__ __forceinline__ ull fma2(ull a, ull b, ull c) {
    ull d; asm("fma.rn.f32x2 %0, %1, %2, %3;" : "=l"(d) : "l"(a), "l"(b), "l"(c)); return d;
}
__device__ __forceinline__ void unpk(ull v, float& lo, float& hi) {
    asm("mov.b64 {%0, %1}, %2;" : "=f"(lo), "=f"(hi) : "l"(v));
}

// exact replica of reference binning
__device__ __forceinline__ int cell_of(float x, float y) {
    const float fx = __fdiv_rn(x - (-51.2f), 0.1f);
    const float fy = __fdiv_rn(y - (-51.2f), 0.1f);
    int px = min(max((int)floorf(fx), 0), 1023);
    int py = min(max((int)floorf(fy), 0), 1023);
    return py * 1024 + px;
}

// ---------------------------------------------------------------------------
// zero g_cnt (8MB) + BN fold
// ---------------------------------------------------------------------------
__global__ void zcnt_kernel(const float* __restrict__ W1, const float* __restrict__ g1,
                            const float* __restrict__ b1, const float* __restrict__ m1,
                            const float* __restrict__ v1,
                            const float* __restrict__ W2, const float* __restrict__ g2,
                            const float* __restrict__ b2, const float* __restrict__ m2,
                            const float* __restrict__ v2) {
    const int bid = blockIdx.x, tid = threadIdx.x;
    int4* cnt4 = (int4*)g_cnt;
    const int4 zi4 = make_int4(0, 0, 0, 0);
    const int ctot4 = BATCH * NCELL / 4;
    for (int i = bid * 256 + tid; i < ctot4; i += 512 * 256) cnt4[i] = zi4;

    if (bid == 0 && tid < 64) {
        const int c = tid;
        const float s1 = g1[c] * rsqrtf(v1[c] + 1e-5f);
        const float s2 = g2[c] * rsqrtf(v2[c] + 1e-5f);
        g_fold[640 + c]  = b1[c] - m1[c] * s1;
        g_fold[4800 + c] = b2[c] - m2[c] * s2;
#pragma unroll
        for (int f = 0; f < 10; f++) g_fold[f * 64 + c] = W1[f * 64 + c] * s1;
        for (int k = 0; k < 64; k++) g_fold[704 + k * 64 + c] = W2[k * 64 + c] * s2;
    }
}

// ---------------------------------------------------------------------------
// bin: cell per point + histogram + zmean partials
// ---------------------------------------------------------------------------
__global__ void bin_kernel(const float* __restrict__ points,
                           const int* __restrict__ mask) {
    const int b = blockIdx.y, tid = threadIdx.x;
    float s = 0.f, c = 0.f;
    for (int i = blockIdx.x * 256 + tid; i < NPTS; i += ZMB * 256) {
        const float* pp = points + ((size_t)b * NPTS + i) * 5;
        const int cl = cell_of(pp[0], pp[1]);
        const int mk = mask[(size_t)b * NPTS + i] != 0;
        g_cell[b][i] = mk ? cl : -1;
        if (mk) {
            atomicAdd(&g_cnt[b][cl], 1);
            s += pp[2];
            c += 1.f;
        }
    }
#pragma unroll
    for (int o = 16; o; o >>= 1) {
        s += __shfl_xor_sync(0xFFFFFFFFu, s, o);
        c += __shfl_xor_sync(0xFFFFFFFFu, c, o);
    }
    __shared__ float ss[8], sc[8];
    const int w = tid >> 5, l = tid & 31;
    if (l == 0) { ss[w] = s; sc[w] = c; }
    __syncthreads();
    if (tid == 0) {
        float S = 0.f, C = 0.f;
#pragma unroll
        for (int i = 0; i < 8; i++) { S += ss[i]; C += sc[i]; }
        g_part[b][0][blockIdx.x] = S;
        g_part[b][1][blockIdx.x] = C;
    }
}

// ---------------------------------------------------------------------------
// scan1: per-4096-cell-chunk exclusive scan (warp-shuffle), 4 cells/thread
// ---------------------------------------------------------------------------
__global__ void scan1_kernel() {
    const int b = blockIdx.y, bx = blockIdx.x, tid = threadIdx.x;
    const int base = bx * 4096 + tid * 4;
    const int4 v = *(const int4*)&g_cnt[b][base];
    const int tsum = v.x + v.y + v.z + v.w;
    int s = tsum;
    const int lane = tid & 31, wid = tid >> 5;
#pragma unroll
    for (int o = 1; o < 32; o <<= 1) {
        int t = __shfl_up_sync(0xFFFFFFFFu, s, o);
        if (lane >= o) s += t;
    }
    __shared__ int wsum[32];
    if (lane == 31) wsum[wid] = s;
    __syncthreads();
    if (wid == 0) {
        int w = wsum[lane];
#pragma unroll
        for (int o = 1; o < 32; o <<= 1) {
            int t = __shfl_up_sync(0xFFFFFFFFu, w, o);
            if (lane >= o) w += t;
        }
        wsum[lane] = w;
    }
    __syncthreads();
    const int wbase = wid ? wsum[wid - 1] : 0;
    const int excl = wbase + s - tsum;
    int4 e;
    e.x = excl; e.y = e.x + v.x; e.z = e.y + v.y; e.w = e.z + v.z;
    *(int4*)&g_cursor[b][base] = e;
    if (tid == 1023) g_bsum[b][bx] = e.w + v.w;
}

// ---------------------------------------------------------------------------
// scatter: inline scan of 256 chunk sums + sorted-list build
// ---------------------------------------------------------------------------
__global__ void scatter_kernel() {
    const int b = blockIdx.y, bx = blockIdx.x, tid = threadIdx.x;
    __shared__ int s_boff[256];
    __shared__ int wsum[8];

    // inline exclusive scan of g_bsum[b][0..255]
    {
        const int v = g_bsum[b][tid];
        int s = v;
        const int lane = tid & 31, wid = tid >> 5;
#pragma unroll
        for (int o = 1; o < 32; o <<= 1) {
            int t = __shfl_up_sync(0xFFFFFFFFu, s, o);
            if (lane >= o) s += t;
        }
        if (lane == 31) wsum[wid] = s;
        __syncthreads();
        if (tid < 8) {
            int w = wsum[tid];
#pragma unroll
            for (int o = 1; o < 8; o <<= 1) {
                int t = __shfl_up_sync(0xFFu, w, o);
                if (tid >= o) w += t;
            }
            wsum[tid] = w;
        }
        __syncthreads();
        const int excl = ((tid >> 5) ? wsum[(tid >> 5) - 1] : 0) + s - v;
        s_boff[tid] = excl;
        if (bx == 0 && tid == 255) g_nvalid[b] = excl + v;
        __syncthreads();
    }

    for (int i = bx * 256 + tid; i < NPTS; i += 128 * 256) {
        const int cl = g_cell[b][i];
        if (cl >= 0) {
            const int pos = atomicAdd(&g_cursor[b][cl], 1) + s_boff[cl >> 12];
            g_idx[b][pos] = i;
        }
    }
}

// ---------------------------------------------------------------------------
// Fused fill + PFN + scatter-max.
// Fill: zero 512MB output. Inactive cells: plain st.128 (pfe never touches
// them). Active cells: RED.MAX(addr,0) — commutes with pfe's scatter-max,
// so NO ordering between fill and compute is needed.
// ---------------------------------------------------------------------------
__global__ __launch_bounds__(MTHREADS, 4)
void pfe_kernel(const float* __restrict__ points,
                float* __restrict__ out) {
    const int tid = threadIdx.x;
    const int b = blockIdx.y;

    // ---------------- fill phase ----------------
    for (int chunk = blockIdx.x; chunk < NCHUNK; chunk += NTILE) {
        const int cbase = chunk * 512 + tid * 4;
        const int4 cnt = *(const int4*)&g_cnt[b][cbase];
        int* dst0 = (int*)out + (((size_t)(b * 64)) << 20) + cbase;
        if ((cnt.x | cnt.y | cnt.z | cnt.w) == 0) {
            const int4 z = make_int4(0, 0, 0, 0);
#pragma unroll 8
            for (int c = 0; c < 64; c++)
                *(int4*)(dst0 + ((size_t)c << 20)) = z;
        } else {
#pragma unroll 4
            for (int c = 0; c < 64; c++) {
                int* d = dst0 + ((size_t)c << 20);
                if (cnt.x) atomicMax(d + 0, 0); else d[0] = 0;
                if (cnt.y) atomicMax(d + 1, 0); else d[1] = 0;
                if (cnt.z) atomicMax(d + 2, 0); else d[2] = 0;
                if (cnt.w) atomicMax(d + 3, 0); else d[3] = 0;
            }
        }
    }

    // ---------------- compute phase ----------------
    const int nvalid = g_nvalid[b];
    const int p0 = blockIdx.x * PPB;
    if (p0 >= nvalid) return;

    extern __shared__ __align__(16) float smem[];
    float* W1s = smem;                  // 640
    float* t1s = smem + 640;            // 64
    float* W2s = smem + 704;            // 4096
    float* t2s = smem + 4800;           // 64
    float* h1s = smem + 4864;           // 64 rows x stride 132
    int* sidx  = (int*)(smem + 13312);  // 128
    int* smk   = sidx + 128;            // 128
    __shared__ float zred;

    for (int i = tid; i < 4864; i += MTHREADS) smem[i] = g_fold[i];
    if (tid < 32) {
        float s = g_part[b][0][tid] + g_part[b][0][tid + 32];
        float c = g_part[b][1][tid] + g_part[b][1][tid + 32];
#pragma unroll
        for (int o = 16; o; o >>= 1) {
            s += __shfl_xor_sync(0xFFFFFFFFu, s, o);
            c += __shfl_xor_sync(0xFFFFFFFFu, c, o);
        }
        if (tid == 0) zred = s / fmaxf(c, 1.0f);
    }
    __syncthreads();
    const float zm = zred;

    // ---------------- Phase A (gather sorted points) ----------------
    {
        const int s = p0 + tid;
        float aug[10];
        int cell = 0, valid = 0;
        if (s < nvalid) {
            const int gi = g_idx[b][s];
            const float* pp = points + ((size_t)b * NPTS + gi) * 5;
            const float x = pp[0], y = pp[1], z = pp[2];
            aug[3] = pp[3]; aug[4] = pp[4];
            const float fx = __fdiv_rn(x - (-51.2f), 0.1f);
            const float fy = __fdiv_rn(y - (-51.2f), 0.1f);
            int px = min(max((int)floorf(fx), 0), 1023);
            int py = min(max((int)floorf(fy), 0), 1023);
            const float pxf = (float)px, pyf = (float)py;
            aug[0] = x; aug[1] = y; aug[2] = z;
            aug[5] = x - (pxf * 0.1f + (-51.2f) + 0.05f);
            aug[6] = y - (pyf * 0.1f + (-51.2f) + 0.05f);
            aug[7] = z - zm;
            aug[8] = x - (pxf * 0.1f + (-51.2f));
            aug[9] = y - (pyf * 0.1f + (-51.2f));
            cell = py * 1024 + px;
            valid = 1;
        } else {
#pragma unroll
            for (int f = 0; f < 10; f++) aug[f] = 0.f;
        }
        sidx[tid] = cell;
        smk[tid] = valid;

        ull h2[32];
        {   // biases via LDS.128 broadcasts
            const ulonglong2* t1q = (const ulonglong2*)t1s;
#pragma unroll
            for (int q = 0; q < 16; q++) {
                const ulonglong2 t = t1q[q];
                h2[2 * q] = t.x; h2[2 * q + 1] = t.y;
            }
        }
        const ulonglong2* W1q = (const ulonglong2*)W1s;
#pragma unroll
        for (int f = 0; f < 10; f++) {
            const ull a = dup2(aug[f]);
#pragma unroll
            for (int q = 0; q < 16; q++) {
                const ulonglong2 w = W1q[f * 16 + q];
                h2[2 * q]     = fma2(a, w.x, h2[2 * q]);
                h2[2 * q + 1] = fma2(a, w.y, h2[2 * q + 1]);
            }
        }
#pragma unroll
        for (int c2 = 0; c2 < 32; c2++) {
            float lo, hi; unpk(h2[c2], lo, hi);
            h1s[(2 * c2) * 132 + tid]     = fmaxf(lo, 0.f);
            h1s[(2 * c2 + 1) * 132 + tid] = fmaxf(hi, 0.f);
        }
    }
    __syncthreads();

    // ---------------- Phase B ----------------
    const int chg = tid & 7;
    const int ptg = tid >> 3;
    const float* hbase = h1s + ptg * 8;
    const ull* W2u = (const ull*)W2s;
    const ulonglong2* t2q = (const ulonglong2*)t2s;

    ull acc[8][4];
    {
        const ulonglong2 tA = t2q[chg * 2 + 0];
        const ulonglong2 tB = t2q[chg * 2 + 1];
#pragma unroll
        for (int i = 0; i < 8; i++) {
            acc[i][0] = tA.x; acc[i][1] = tA.y; acc[i][2] = tB.x; acc[i][3] = tB.y;
        }
    }

#pragma unroll 4
    for (int k = 0; k < 64; k++) {
        const float4 ha = *(const float4*)(hbase + k * 132);
        const float4 hb = *(const float4*)(hbase + k * 132 + 4);
        const ulonglong2 wA = *(const ulonglong2*)(W2u + k * 32 + chg * 4);
        const ulonglong2 wB = *(const ulonglong2*)(W2u + k * 32 + chg * 4 + 2);
        const ull hd[8] = {dup2(ha.x), dup2(ha.y), dup2(ha.z), dup2(ha.w),
                           dup2(hb.x), dup2(hb.y), dup2(hb.z), dup2(hb.w)};
#pragma unroll
        for (int i = 0; i < 8; i++) {
            acc[i][0] = fma2(hd[i], wA.x, acc[i][0]);
            acc[i][1] = fma2(hd[i], wA.y, acc[i][1]);
            acc[i][2] = fma2(hd[i], wB.x, acc[i][2]);
            acc[i][3] = fma2(hd[i], wB.y, acc[i][3]);
        }
    }

    // ---------------- epilogue: run-length dedup + scatter-max ----------------
    int* obase = (int*)out + (((size_t)(b * 64 + chg * 8)) << 20);
    const int base = ptg * 8;

    float rm[8];
#pragma unroll
    for (int j = 0; j < 4; j++) unpk(acc[0][j], rm[2 * j], rm[2 * j + 1]);
    int cur = sidx[base];
    int curv = smk[base];

#pragma unroll
    for (int i = 1; i < 8; i++) {
        const int v = smk[base + i];
        const int cl = sidx[base + i];
        float f[8];
#pragma unroll
        for (int j = 0; j < 4; j++) unpk(acc[i][j], f[2 * j], f[2 * j + 1]);
        if (v && cl == cur) {
#pragma unroll
            for (int t = 0; t < 8; t++) rm[t] = fmaxf(rm[t], f[t]);
        } else {
            if (curv) {
                int* ob = obase + cur;
#pragma unroll
                for (int t = 0; t < 8; t++)
                    if (rm[t] > 0.f) atomicMax(ob + ((size_t)t << 20), __float_as_int(rm[t]));
            }
#pragma unroll
            for (int t = 0; t < 8; t++) rm[t] = f[t];
            cur = cl;
            curv = v;
        }
    }
    if (curv) {
        int* ob = obase + cur;
#pragma unroll
        for (int t = 0; t < 8; t++)
            if (rm[t] > 0.f) atomicMax(ob + ((size_t)t << 20), __float_as_int(rm[t]));
    }
}

// ---------------------------------------------------------------------------
extern "C" void kernel_launch(void* const* d_in, const int* in_sizes, int n_in,
                              void* d_out, int out_size) {
    const float* points = (const float*)d_in[0];
    const int* pmask    = (const int*)d_in[1];
    const float* W1 = (const float*)d_in[2];
    const float* g1 = (const float*)d_in[3];
    const float* b1 = (const float*)d_in[4];
    const float* m1 = (const float*)d_in[5];
    const float* v1 = (const float*)d_in[6];
    const float* W2 = (const float*)d_in[7];
    const float* g2 = (const float*)d_in[8];
    const float* b2 = (const float*)d_in[9];
    const float* m2 = (const float*)d_in[10];
    const float* v2 = (const float*)d_in[11];
    float* out = (float*)d_out;

    cudaFuncSetAttribute(pfe_kernel, cudaFuncAttributeMaxDynamicSharedMemorySize, SMEM_BYTES);

    zcnt_kernel<<<512, 256>>>(W1, g1, b1, m1, v1, W2, g2, b2, m2, v2);

    dim3 bg(ZMB, BATCH);
    bin_kernel<<<bg, 256>>>(points, pmask);

    dim3 s1g(256, BATCH);
    scan1_kernel<<<s1g, 1024>>>();

    dim3 scg(128, BATCH);
    scatter_kernel<<<scg, 256>>>();

    dim3 mg(NTILE, BATCH);
    pfe_kernel<<<mg, MTHREADS, SMEM_BYTES>>>(points, out);
}